// round 7
// baseline (speedup 1.0000x reference)
#include <cuda_runtime.h>
#include <cstdint>

#define IN_SIZE  256
#define N_NODES  1024
#define DEG      32
#define BATCH    16384
#define OUT_SIZE 16

#define BT      40                      // batch columns per CTA
#define NTHR    320                     // 10 warps
#define STRIDE  41                      // words per activation row (odd -> bank spread)
#define ROWB    (STRIDE * 4)            // 164 B per row
#define NROWS2  (IN_SIZE + N_NODES + 1) // 1281 (row 1280 = dummy scratch)
#define SMEM_ACT (NROWS2 * STRIDE)      // floats: 52521
#define MAXSLOT 2112                    // worst case: 1024 levels, all padded to 2
#define SMEM_BYTES (SMEM_ACT * 4 + (MAXSLOT + 8) * 4)
#define NCTA    ((BATCH + BT - 1) / BT) // 410

// ---------------- device-global scratch (static, no allocs) ----------------
__device__ int      g_sched[MAXSLOT];          // slot -> node id (-1 = dummy)
__device__ int      g_nslots;                  // even
__device__ uint4    g_pairs2[1024 * 32 + 64];  // per-step packed (off,w) stream
__device__ unsigned g_stoff[MAXSLOT + 64];     // per-slot store byte offset

// ---------------- prepass A: depth + level schedule (1 block) ----------------
__device__ __forceinline__ int redmax32(int v) {
    int r;
    asm("redux.sync.max.s32 %0, %1, 0xffffffff;" : "=r"(r) : "r"(v));
    return r;
}

#define PA_SMEM ((32768 + 1280 + 1025 + 1025 + 2) * 4)

__global__ void schedule_kernel(const int* __restrict__ idx) {
    extern __shared__ int sm[];
    int* s_idx = sm;                    // [1024*32]
    int* s_dep = sm + 32768;            // [1280] depth per activation row
    int* s_cnt = s_dep + 1280;          // [1025] level histogram
    int* s_off = s_cnt + 1025;          // [1025] level start slot
    int* s_aux = s_off + 1025;          // [2]: maxd, nslots
    const int tid = threadIdx.x;

    {   // stage idx; init
        const int4* src = (const int4*)idx;
        int4* dst = (int4*)s_idx;
        for (int i = tid; i < 8192; i += 256) dst[i] = src[i];
        for (int i = tid; i < 256;  i += 256) s_dep[i] = 0;
        for (int i = tid; i < 1025; i += 256) s_cnt[i] = 0;
        if (tid == 0) { s_aux[0] = 0; }
    }
    __syncthreads();

    // ---- sequential depth, 4-node speculative window (warp 0) ----
    if (tid < 32) {
        const int lane = tid;
        for (int base = 0; base < N_NODES; base += 4) {
            const int lim = IN_SIZE + base;
            int r0 = s_idx[(base + 0) * 32 + lane];
            int r1 = s_idx[(base + 1) * 32 + lane];
            int r2 = s_idx[(base + 2) * 32 + lane];
            int r3 = s_idx[(base + 3) * 32 + lane];
            // refs to rows >= lim are in-window (rows lim..lim+2); patched below
            int v0 = (r0 < lim) ? s_dep[r0] : 0;
            int v1 = (r1 < lim) ? s_dep[r1] : 0;
            int v2 = (r2 < lim) ? s_dep[r2] : 0;
            int v3 = (r3 < lim) ? s_dep[r3] : 0;
            int m0 = redmax32(v0), m1 = redmax32(v1);
            int m2 = redmax32(v2), m3 = redmax32(v3);
            bool b10 = __any_sync(0xffffffffu, r1 == lim);
            bool b20 = __any_sync(0xffffffffu, r2 == lim);
            bool b21 = __any_sync(0xffffffffu, r2 == lim + 1);
            bool b30 = __any_sync(0xffffffffu, r3 == lim);
            bool b31 = __any_sync(0xffffffffu, r3 == lim + 1);
            bool b32 = __any_sync(0xffffffffu, r3 == lim + 2);
            int d0 = m0 + 1;
            int d1 = max(m1, b10 ? d0 : 0) + 1;
            int d2 = max(max(m2, b20 ? d0 : 0), b21 ? d1 : 0) + 1;
            int d3 = max(max(m3, b30 ? d0 : 0), max(b31 ? d1 : 0, b32 ? d2 : 0)) + 1;
            if (lane == 0) {
                s_dep[lim]     = d0;  s_dep[lim + 1] = d1;
                s_dep[lim + 2] = d2;  s_dep[lim + 3] = d3;
            }
            __syncwarp();   // order lane0's STS before next window's cross-lane LDS
        }
    }
    __syncthreads();

    // ---- level histogram + max level ----
    for (int i = tid; i < N_NODES; i += 256) {
        int l = s_dep[IN_SIZE + i];
        atomicAdd(&s_cnt[l], 1);
        atomicMax(&s_aux[0], l);
    }
    __syncthreads();

    // ---- level offsets, padded to even (dummy fills the gap) ----
    if (tid == 0) {
        int acc = 0, md = s_aux[0];
        for (int l = 1; l <= md; l++) {
            s_off[l] = acc;
            acc += (s_cnt[l] + 1) & ~1;
        }
        s_aux[1] = acc;
        g_nslots = acc;
    }
    __syncthreads();

    const int nslots = s_aux[1];
    for (int t = tid; t < nslots; t += 256) g_sched[t] = -1;   // dummies by default
    __syncthreads();

    // ---- stable placement (warp 0, 32 nodes per chunk via match_any) ----
    if (tid < 32) {
        const int lane = tid;
        for (int c = 0; c < 32; c++) {
            int i = c * 32 + lane;
            int l = s_dep[IN_SIZE + i];
            unsigned mask = __match_any_sync(0xffffffffu, l);
            int rank = __popc(mask & ((1u << lane) - 1u));
            int base_ = s_off[l];
            g_sched[base_ + rank] = i;
            if ((int)(__ffs(mask) - 1) == lane) s_off[l] = base_ + __popc(mask);
            __syncwarp();   // order s_off update before next chunk's reads
        }
    }
}

// ---------------- prepass B: pack pairs + store offsets (parallel) ----------------
__global__ void pack2(const int* __restrict__ idx, const float* __restrict__ w) {
    int e = blockIdx.x * blockDim.x + threadIdx.x;
    int nslots = g_nslots;
    int nsteps = nslots >> 1;

    if (e < nsteps * 32) {
        int s = e >> 5, r = e & 31;
        int np = r >> 4, dg = (r >> 2) & 3, k = r & 3;
        int node = g_sched[2 * s + np];
        if (node >= 0) {
            int d0 = 8 * dg + 2 * k;
            g_pairs2[e] = make_uint4(
                (unsigned)idx[node * DEG + d0]     * (unsigned)ROWB,
                __float_as_uint(w[node * DEG + d0]),
                (unsigned)idx[node * DEG + d0 + 1] * (unsigned)ROWB,
                __float_as_uint(w[node * DEG + d0 + 1]));
        } else {
            g_pairs2[e] = make_uint4(0u, 0u, 0u, 0u);   // row0 gathers, w=0
        }
    } else if (e < 1024 * 32 + 64) {
        g_pairs2[e] = make_uint4(0u, 0u, 0u, 0u);
    }

    if (e < MAXSLOT + 64) {
        unsigned off = (unsigned)(IN_SIZE + N_NODES) * (unsigned)ROWB;  // scratch row
        if (e < nslots) {
            int node = g_sched[e];
            if (node >= 0) off = (unsigned)(IN_SIZE + node) * (unsigned)ROWB;
        }
        g_stoff[e] = off;
    }
}

// Exact tanh(x) = 1 - 2/(exp(2x)+1); 2x MUFU, ~1e-6 abs err, saturates correctly.
__device__ __forceinline__ float ftanh(float x) {
    float e = __expf(2.0f * x);
    return 1.0f - __fdividef(2.0f, e + 1.0f);
}

extern __shared__ float As[];   // [NROWS2][STRIDE] activations; then stoff cache

__global__ void __launch_bounds__(NTHR, 1)
ne_kernel(const float* __restrict__ x, float* __restrict__ out) {
    const int tid = threadIdx.x;
    const int b0  = blockIdx.x * BT;
    unsigned* s_stoff = (unsigned*)(As + SMEM_ACT);
    const int nslots = g_nslots;
    const int NS = nslots >> 1;

    // ---- Stage inputs transposed: As[i][bl] = x[b0+bl][i]; cache store offsets ----
    {
        int bl = tid >> 3;          // 0..39
        int ts = tid & 7;
        if (b0 + bl < BATCH) {
            const float4* xr = (const float4*)(x + (size_t)(b0 + bl) * IN_SIZE);
            #pragma unroll
            for (int k = ts; k < IN_SIZE / 4; k += 8) {
                float4 v = xr[k];
                int i = k * 4;
                As[(i + 0) * STRIDE + bl] = v.x;
                As[(i + 1) * STRIDE + bl] = v.y;
                As[(i + 2) * STRIDE + bl] = v.z;
                As[(i + 3) * STRIDE + bl] = v.w;
            }
        }
        for (int i = tid; i < nslots + 2; i += NTHR) s_stoff[i] = g_stoff[i];
    }
    __syncthreads();

    // ---- Lane layout: np (bit4) x dg (bits 3:2) x bb (bits 1:0) ----
    const int lane = tid & 31;
    const int warp = tid >> 5;
    const int np   = lane >> 4;
    const int dg   = (lane >> 2) & 3;
    const int bb   = lane & 3;
    const int col  = warp * 4 + bb;      // warp-private batch column
    const bool wr  = (dg == 0);

    const char* Ac  = (const char*)As + col * 4;
    char*       Abs = (char*)As + col * 4;

    const uint4* pq = g_pairs2 + (lane & ~3);

    // 1-step software pipeline
    uint4 C0 = pq[0], C1 = pq[1], C2 = pq[2], C3 = pq[3];
    pq += 32;
    unsigned so = s_stoff[np];
    const unsigned* sop = s_stoff + 2 + np;

    for (int s = 0; s < NS; s++) {
        uint4 N0 = pq[0], N1 = pq[1], N2 = pq[2], N3 = pq[3];
        pq += 32;
        unsigned so_n = *sop;  sop += 2;

        float a0 = 0.f, a1 = 0.f;
        {
            float v0 = *(const float*)(Ac + C0.x);
            float v1 = *(const float*)(Ac + C0.z);
            float v2 = *(const float*)(Ac + C1.x);
            float v3 = *(const float*)(Ac + C1.z);
            float v4 = *(const float*)(Ac + C2.x);
            float v5 = *(const float*)(Ac + C2.z);
            float v6 = *(const float*)(Ac + C3.x);
            float v7 = *(const float*)(Ac + C3.z);
            a0 = __fmaf_rn(__uint_as_float(C0.y), v0, a0);
            a1 = __fmaf_rn(__uint_as_float(C0.w), v1, a1);
            a0 = __fmaf_rn(__uint_as_float(C1.y), v2, a0);
            a1 = __fmaf_rn(__uint_as_float(C1.w), v3, a1);
            a0 = __fmaf_rn(__uint_as_float(C2.y), v4, a0);
            a1 = __fmaf_rn(__uint_as_float(C2.w), v5, a1);
            a0 = __fmaf_rn(__uint_as_float(C3.y), v6, a0);
            a1 = __fmaf_rn(__uint_as_float(C3.w), v7, a1);
        }
        float sum = a0 + a1;
        sum += __shfl_xor_sync(0xffffffffu, sum, 4);   // reduce over dg
        sum += __shfl_xor_sync(0xffffffffu, sum, 8);   // (np, bb preserved)
        float t = ftanh(sum);
        if (wr) *(float*)(Abs + so) = t;               // this slot's node row

        so = so_n;
        C0 = N0; C1 = N1; C2 = N2; C3 = N3;
    }

    // ---- Emit last OUT_SIZE node outputs: out[o][b0+c] (cross-warp -> barrier) ----
    __syncthreads();
    #pragma unroll
    for (int r = 0; r < 2; r++) {
        int e = r * NTHR + tid;          // 0..639
        int o = e / BT;                  // 0..15
        int c = e - o * BT;              // 0..39
        if (b0 + c < BATCH) {
            float v = *(const float*)((const char*)As +
                         (size_t)(IN_SIZE + N_NODES - OUT_SIZE + o) * ROWB + c * 4);
            out[(size_t)o * BATCH + b0 + c] = v;
        }
    }
}

extern "C" void kernel_launch(void* const* d_in, const int* in_sizes, int n_in,
                              void* d_out, int out_size) {
    const float* x   = (const float*)d_in[0];   // [16384, 256] f32
    const float* w   = (const float*)d_in[1];   // [1024, 32]   f32
    const int*   idx = (const int*)  d_in[2];   // [1024, 32]   i32
    float*       out = (float*)d_out;           // [16, 16384]  f32

    cudaFuncSetAttribute(schedule_kernel, cudaFuncAttributeMaxDynamicSharedMemorySize, PA_SMEM);
    cudaFuncSetAttribute(ne_kernel, cudaFuncAttributeMaxDynamicSharedMemorySize, SMEM_BYTES);

    schedule_kernel<<<1, 256, PA_SMEM>>>(idx);
    pack2<<<(1024 * 32 + 64 + 255) / 256, 256>>>(idx, w);
    ne_kernel<<<NCTA, NTHR, SMEM_BYTES>>>(x, out);
}

// round 8
// speedup vs baseline: 1.4598x; 1.4598x over previous
#include <cuda_runtime.h>
#include <cstdint>

#define IN_SIZE  256
#define N_NODES  1024
#define DEG      32
#define BATCH    16384
#define OUT_SIZE 16

#define BT      32                      // batch columns per CTA (= warp width)
#define NTHR    384                     // 12 warps
#define NWARP   12
#define NROWS   (IN_SIZE + N_NODES)     // 1280
#define NCTA    (BATCH / BT)            // 512
#define REC     17                      // uint4 per node record (16 pair-chunks + meta)
#define PB_NODES 64                     // max nodes per level chunk
#define PB_U4   (PB_NODES * REC)        // 1088 uint4 per buffer
#define AS_FLOATS (NROWS * BT)          // 40960 (row stride 32 words = 128 B)
#define MAXB    1100                    // max level-chunk boundaries
#define SMEM_BYTES (AS_FLOATS * 4 + 2 * PB_U4 * 16 + (MAXB + 4) * 4)

// ---------------- device globals ----------------
__device__ int   g_sched[N_NODES];      // slot -> node id (level-grouped)
__device__ int   g_nlvl;                // number of level chunks
__device__ int   g_lvloff[MAXB];        // chunk boundaries B[0..nlvl]
__device__ uint4 g_prec[N_NODES * REC]; // slot-major node records

// ---------------- prepass A: depth + level schedule (1 block) ----------------
__device__ __forceinline__ int redmax32(int v) {
    int r;
    asm("redux.sync.max.s32 %0, %1, 0xffffffff;" : "=r"(r) : "r"(v));
    return r;
}

#define PA_SMEM ((32768 + 1280 + 1025 + 1025 + 2) * 4)

__global__ void schedule_kernel(const int* __restrict__ idx) {
    extern __shared__ int sm[];
    int* s_idx = sm;                    // [1024*32]
    int* s_dep = sm + 32768;            // [1280] depth per activation row
    int* s_cnt = s_dep + 1280;          // [1025] level histogram
    int* s_off = s_cnt + 1025;          // [1025] level start slot (placement cursor)
    int* s_aux = s_off + 1025;          // [2]: maxd
    const int tid = threadIdx.x;

    {   // stage idx; init
        const int4* src = (const int4*)idx;
        int4* dst = (int4*)s_idx;
        for (int i = tid; i < 8192; i += 256) dst[i] = src[i];
        for (int i = tid; i < 256;  i += 256) s_dep[i] = 0;
        for (int i = tid; i < 1025; i += 256) s_cnt[i] = 0;
        if (tid == 0) s_aux[0] = 0;
    }
    __syncthreads();

    // ---- sequential depth, 4-node speculative window (warp 0) ----
    if (tid < 32) {
        const int lane = tid;
        for (int base = 0; base < N_NODES; base += 4) {
            const int lim = IN_SIZE + base;
            int r0 = s_idx[(base + 0) * 32 + lane];
            int r1 = s_idx[(base + 1) * 32 + lane];
            int r2 = s_idx[(base + 2) * 32 + lane];
            int r3 = s_idx[(base + 3) * 32 + lane];
            int v0 = (r0 < lim) ? s_dep[r0] : 0;
            int v1 = (r1 < lim) ? s_dep[r1] : 0;
            int v2 = (r2 < lim) ? s_dep[r2] : 0;
            int v3 = (r3 < lim) ? s_dep[r3] : 0;
            int m0 = redmax32(v0), m1 = redmax32(v1);
            int m2 = redmax32(v2), m3 = redmax32(v3);
            bool b10 = __any_sync(0xffffffffu, r1 == lim);
            bool b20 = __any_sync(0xffffffffu, r2 == lim);
            bool b21 = __any_sync(0xffffffffu, r2 == lim + 1);
            bool b30 = __any_sync(0xffffffffu, r3 == lim);
            bool b31 = __any_sync(0xffffffffu, r3 == lim + 1);
            bool b32 = __any_sync(0xffffffffu, r3 == lim + 2);
            int d0 = m0 + 1;
            int d1 = max(m1, b10 ? d0 : 0) + 1;
            int d2 = max(max(m2, b20 ? d0 : 0), b21 ? d1 : 0) + 1;
            int d3 = max(max(m3, b30 ? d0 : 0), max(b31 ? d1 : 0, b32 ? d2 : 0)) + 1;
            if (lane == 0) {
                s_dep[lim]     = d0;  s_dep[lim + 1] = d1;
                s_dep[lim + 2] = d2;  s_dep[lim + 3] = d3;
            }
            __syncwarp();
        }
    }
    __syncthreads();

    // ---- level histogram + max level ----
    for (int i = tid; i < N_NODES; i += 256) {
        int l = s_dep[IN_SIZE + i];
        atomicAdd(&s_cnt[l], 1);
        atomicMax(&s_aux[0], l);
    }
    __syncthreads();

    // ---- level starts + chunked boundaries (<= PB_NODES per chunk) ----
    if (tid == 0) {
        int acc = 0, nb = 0, md = s_aux[0];
        g_lvloff[0] = 0;
        for (int l = 1; l <= md; l++) {
            s_off[l] = acc;
            int c = s_cnt[l];
            while (c > 0) {
                int take = (c < PB_NODES) ? c : PB_NODES;
                acc += take;  c -= take;
                g_lvloff[++nb] = acc;
            }
        }
        g_nlvl = nb;
    }
    __syncthreads();

    // ---- stable placement (warp 0, match_any) ----
    if (tid < 32) {
        const int lane = tid;
        for (int c = 0; c < 32; c++) {
            int i = c * 32 + lane;
            int l = s_dep[IN_SIZE + i];
            unsigned mask = __match_any_sync(0xffffffffu, l);
            int rank = __popc(mask & ((1u << lane) - 1u));
            int base_ = s_off[l];
            g_sched[base_ + rank] = i;
            if ((int)(__ffs(mask) - 1) == lane) s_off[l] = base_ + __popc(mask);
            __syncwarp();
        }
    }
}

// ---------------- prepass B: pack slot-major node records ----------------
// record[s]: j<16 -> { idx(2j)<<7, w(2j), idx(2j+1)<<7, w(2j+1) };  j==16 -> { storeoff,0,0,0 }
__global__ void pack3(const int* __restrict__ idx, const float* __restrict__ w) {
    int e = blockIdx.x * blockDim.x + threadIdx.x;
    if (e >= N_NODES * REC) return;
    int s = e / REC, j = e - s * REC;
    int node = g_sched[s];
    if (j < 16) {
        int d0 = 2 * j;
        g_prec[e] = make_uint4((unsigned)idx[node * DEG + d0]     << 7,
                               __float_as_uint(w[node * DEG + d0]),
                               (unsigned)idx[node * DEG + d0 + 1] << 7,
                               __float_as_uint(w[node * DEG + d0 + 1]));
    } else {
        g_prec[e] = make_uint4((unsigned)(IN_SIZE + node) << 7, 0u, 0u, 0u);
    }
}

// Exact tanh(x) = 1 - 2/(exp(2x)+1); ~1e-6 abs err, saturates correctly.
__device__ __forceinline__ float ftanh(float x) {
    float e = __expf(2.0f * x);
    return 1.0f - __fdividef(2.0f, e + 1.0f);
}

__device__ __forceinline__ void cp16(unsigned dst_smem, const void* src) {
    asm volatile("cp.async.cg.shared.global [%0], [%1], 16;"
                 :: "r"(dst_smem), "l"(src) : "memory");
}
__device__ __forceinline__ void cp_commit() { asm volatile("cp.async.commit_group;" ::: "memory"); }
__device__ __forceinline__ void cp_wait0()  { asm volatile("cp.async.wait_group 0;" ::: "memory"); }

extern __shared__ float SM[];

__global__ void __launch_bounds__(NTHR, 1)
ne_kernel(const float* __restrict__ x, float* __restrict__ out) {
    const int tid  = threadIdx.x;
    const int lane = tid & 31;
    const int wid  = tid >> 5;
    const int b0   = blockIdx.x * BT;

    float* As   = SM;                                   // [1280][32] floats, row = 128 B
    uint4* pbuf = (uint4*)(SM + AS_FLOATS);             // 2 x PB_U4
    int*   s_lv = (int*)(pbuf + 2 * PB_U4);             // boundaries
    const unsigned pbuf_u32 = (unsigned)__cvta_generic_to_shared(pbuf);

    const int nb = g_nlvl;

    // ---- stage inputs transposed: As[row][col] = x[b0+col][row]; cache boundaries ----
    {
        int bl = tid >> 3;          // 0..47 (guard)
        int ts = tid & 7;
        if (bl < BT) {
            const float4* xr = (const float4*)(x + (size_t)(b0 + bl) * IN_SIZE);
            #pragma unroll
            for (int k = ts; k < IN_SIZE / 4; k += 8) {
                float4 v = xr[k];
                int i = k * 4;
                As[(i + 0) * BT + bl] = v.x;
                As[(i + 1) * BT + bl] = v.y;
                As[(i + 2) * BT + bl] = v.z;
                As[(i + 3) * BT + bl] = v.w;
            }
        }
        for (int i = tid; i <= nb; i += NTHR) s_lv[i] = g_lvloff[i];
    }
    __syncthreads();

    char* Acb = (char*)As + (lane << 2);    // this lane's column base

    // ---- prologue: stage chunk 0 into buffer 0 ----
    {
        int s0 = s_lv[0], s1 = s_lv[1];
        int n16 = (s1 - s0) * REC;
        for (int i = tid; i < n16; i += NTHR)
            cp16(pbuf_u32 + i * 16, g_prec + s0 * REC + i);
        cp_commit(); cp_wait0();
    }
    __syncthreads();

    // ---- level-chunk loop ----
    for (int k = 0; k < nb; k++) {
        // stage next chunk into the other buffer (overlapped with compute)
        if (k + 1 < nb) {
            int t0 = s_lv[k + 1], t1 = s_lv[k + 2];
            int n16 = (t1 - t0) * REC;
            unsigned dst = pbuf_u32 + ((k + 1) & 1) * (PB_U4 * 16);
            for (int i = tid; i < n16; i += NTHR)
                cp16(dst + i * 16, g_prec + t0 * REC + i);
        }
        cp_commit();

        // compute this chunk: one warp per node, lane = column
        int s0 = s_lv[k], s1 = s_lv[k + 1];
        const uint4* rec = pbuf + (k & 1) * PB_U4;
        for (int sl = s0 + wid; sl < s1; sl += NWARP) {
            const uint4* P = rec + (sl - s0) * REC;
            unsigned so = P[16].x;                      // uniform store offset
            float a0 = 0.f, a1 = 0.f, a2 = 0.f, a3 = 0.f;
            #pragma unroll
            for (int j = 0; j < 16; j += 2) {
                uint4 p = P[j], q = P[j + 1];           // uniform LDS.128 (broadcast)
                a0 = __fmaf_rn(__uint_as_float(p.y), *(const float*)(Acb + p.x), a0);
                a1 = __fmaf_rn(__uint_as_float(p.w), *(const float*)(Acb + p.z), a1);
                a2 = __fmaf_rn(__uint_as_float(q.y), *(const float*)(Acb + q.x), a2);
                a3 = __fmaf_rn(__uint_as_float(q.w), *(const float*)(Acb + q.z), a3);
            }
            float t = ftanh((a0 + a2) + (a1 + a3));
            *(float*)((char*)As + so + (lane << 2)) = t;    // conflict-free row store
        }

        cp_wait0();
        __syncthreads();
    }

    // ---- emit last OUT_SIZE node rows (by original id): out[o][b0+c] ----
    for (int e = tid; e < OUT_SIZE * BT; e += NTHR) {
        int o = e >> 5, c = e & 31;
        float v = As[(IN_SIZE + N_NODES - OUT_SIZE + o) * BT + c];
        out[(size_t)o * BATCH + b0 + c] = v;
    }
}

extern "C" void kernel_launch(void* const* d_in, const int* in_sizes, int n_in,
                              void* d_out, int out_size) {
    const float* x   = (const float*)d_in[0];   // [16384, 256] f32
    const float* w   = (const float*)d_in[1];   // [1024, 32]   f32
    const int*   idx = (const int*)  d_in[2];   // [1024, 32]   i32
    float*       out = (float*)d_out;           // [16, 16384]  f32

    cudaFuncSetAttribute(schedule_kernel, cudaFuncAttributeMaxDynamicSharedMemorySize, PA_SMEM);
    cudaFuncSetAttribute(ne_kernel, cudaFuncAttributeMaxDynamicSharedMemorySize, SMEM_BYTES);

    schedule_kernel<<<1, 256, PA_SMEM>>>(idx);
    pack3<<<(N_NODES * REC + 255) / 256, 256>>>(idx, w);
    ne_kernel<<<NCTA, NTHR, SMEM_BYTES>>>(x, out);
}